// round 16
// baseline (speedup 1.0000x reference)
#include <cuda_runtime.h>
#include <cuda_fp16.h>
#include <math.h>
#include <stdint.h>

// Problem constants (fixed by setup_inputs)
#define NN 50000
#define EE 800000
#define DD 128
#define LL 2
#define NCHUNK ((NN + 1023) / 1024)
#define CONVN (NN * DD / 4)

// ---------------- scratch (static __device__ globals; no allocation) ----------------
// g_cursor zeroed inside k_countscan each call (module-load zero-init covers call #1;
// countscan runs before k_prep's fill, so the invariant holds).
__device__ float g_bias[LL * 384];
__device__ float g_invdeg[NN];
__device__ int g_rowptr[NN + 1];
__device__ int g_cursor[NN];
__device__ int g_esrc[EE];

__device__ __align__(16) __half g_Z[NN * DD];
__device__ __align__(16) __half g_HX[NN * DD];
__device__ __align__(16) __half g_inp[NN * DD];
__device__ __align__(16) __half g_h[LL * NN * DD];
__device__ __align__(16) __half g_agga[NN * DD];
__device__ __align__(16) __half g_aggb[NN * DD];
__device__ __align__(16) __half g_rh[NN * DD];
__device__ __align__(16) __half g_W1T[LL * 384 * 512];
__device__ __align__(16) __half g_W2T[LL * 128 * 256];

// ---------------- helpers ----------------
__device__ __forceinline__ uint32_t smem_u32(const void* p) {
    uint32_t a;
    asm("{ .reg .u64 t; cvta.to.shared.u64 t, %1; cvt.u32.u64 %0, t; }" : "=r"(a) : "l"(p));
    return a;
}
__device__ __forceinline__ void ldsm4(uint32_t* f, uint32_t addr) {
    asm volatile("ldmatrix.sync.aligned.m8n8.x4.shared.b16 {%0,%1,%2,%3}, [%4];"
                 : "=r"(f[0]), "=r"(f[1]), "=r"(f[2]), "=r"(f[3]) : "r"(addr));
}
__device__ __forceinline__ void mma16816(float* c, const uint32_t* a, uint32_t b0, uint32_t b1) {
    asm volatile(
        "mma.sync.aligned.m16n8k16.row.col.f32.f16.f16.f32 "
        "{%0,%1,%2,%3}, {%4,%5,%6,%7}, {%8,%9}, {%0,%1,%2,%3};"
        : "+f"(c[0]), "+f"(c[1]), "+f"(c[2]), "+f"(c[3])
        : "r"(a[0]), "r"(a[1]), "r"(a[2]), "r"(a[3]), "r"(b0), "r"(b1));
}
__device__ __forceinline__ void cpa16(uint32_t dst, const void* src, int sz) {
    asm volatile("cp.async.cg.shared.global [%0], [%1], 16, %2;"
                 :: "r"(dst), "l"(src), "r"(sz) : "memory");
}
#define CPA_COMMIT() asm volatile("cp.async.commit_group;" ::: "memory")
#define CPA_WAIT1()  asm volatile("cp.async.wait_group 1;" ::: "memory")

__device__ __forceinline__ void store_h4(__half* d, float4 v) {
    __half2 h0 = __floats2half2_rn(v.x, v.y);
    __half2 h1 = __floats2half2_rn(v.z, v.w);
    uint2 u;
    u.x = *(uint32_t*)&h0;
    u.y = *(uint32_t*)&h1;
    *(uint2*)d = u;
}
__device__ __forceinline__ void store_h2(__half* d, float a, float b) {
    __half2 hh = __floats2half2_rn(a, b);
    *(uint32_t*)d = *(uint32_t*)&hh;
}
// fast MUFU-path transcendentals (rel err ~1e-6, invisible vs fp16 path error)
__device__ __forceinline__ float sigf(float x) { return 1.0f / (1.0f + __expf(-x)); }
__device__ __forceinline__ float tanh_fast(float x) {
    float t = __expf(2.0f * x);
    return 1.0f - 2.0f / (t + 1.0f);
}

// SMEM tile geometry: padded row stride 80B (conflict-free ldmatrix)
#define TROW 80
#define ATB (128 * TROW)           // A subtile: 128 rows x 32 cols  (10240)
#define BTB (64 * TROW)            // B subtile: 64 rows x 32 cols (5120)
#define SUB1 (ATB + BTB)           // 15360: one K32 pipeline stage
#define NSTG 3
#define GSMEM1 (NSTG * SUB1)       // 46080: 3-stage ring -> 4 CTAs/SM

// precomputed per-thread tile-load state (32-bit offsets; all < 2^31)
struct Pre {
    uint32_t sm0, sm1;
    uint32_t a0, a1;
    int az0, az1;
    uint32_t b0, b1;
};

__device__ __forceinline__ Pre make_pre(int t, int row0, int col0, int strideB) {
    Pre p;
    int q = t & 3;
    int r0 = t >> 2, r1 = r0 + 64;
    p.sm0 = (uint32_t)(r0 * TROW + q * 16);
    p.sm1 = (uint32_t)(r1 * TROW + q * 16);
    int gr0 = row0 + r0, gr1 = row0 + r1;
    p.az0 = gr0 < NN ? 16 : 0;
    p.az1 = gr1 < NN ? 16 : 0;
    if (gr0 >= NN) gr0 = 0;
    if (gr1 >= NN) gr1 = 0;
    p.a0 = (uint32_t)(gr0 * 128 + q * 8);
    p.a1 = (uint32_t)(gr1 * 128 + q * 8);
    p.b0 = (uint32_t)((col0 + r0) * strideB + q * 8);
    p.b1 = (uint32_t)((col0 + r1) * strideB + q * 8);
    return p;
}

// one K32 stage: A 128x32 + B 64x32
__device__ __forceinline__ void load_sub1(uint32_t buf,
                                          const __half* __restrict__ a,
                                          const __half* __restrict__ b,
                                          int colA, int colB, const Pre& p) {
    cpa16(buf + p.sm0,       a + p.a0 + colA, p.az0);
    cpa16(buf + p.sm1,       a + p.a1 + colA, p.az1);
    cpa16(buf + ATB + p.sm0, b + p.b0 + colB, 16);
}

// ---------------- CSR: fused count+scan (+ cursor zeroing) ----------------
__global__ void __launch_bounds__(1024)
k_countscan(const int* __restrict__ dst) {
    __shared__ int hist[1024];
    __shared__ int ws[32];
    __shared__ int sbase;
    int b = blockIdx.x, t = threadIdx.x;
    int lane = t & 31, wid = t >> 5;
    hist[t] = 0;
    __syncthreads();

    int lo = b << 10;
    int pre = 0;
    const int4* d4 = (const int4*)dst;
    for (int e = t; e < EE / 4; e += 1024) {
        int4 v = __ldg(d4 + e);
        pre += (v.x < lo) + (v.y < lo) + (v.z < lo) + (v.w < lo);
        int dx;
        dx = v.x - lo; if ((unsigned)dx < 1024u) atomicAdd(&hist[dx], 1);
        dx = v.y - lo; if ((unsigned)dx < 1024u) atomicAdd(&hist[dx], 1);
        dx = v.z - lo; if ((unsigned)dx < 1024u) atomicAdd(&hist[dx], 1);
        dx = v.w - lo; if ((unsigned)dx < 1024u) atomicAdd(&hist[dx], 1);
    }
#pragma unroll
    for (int o = 16; o > 0; o >>= 1) pre += __shfl_down_sync(0xffffffffu, pre, o);
    if (lane == 0) ws[wid] = pre;
    __syncthreads();
    if (t < 32) {
        int s = ws[t];
#pragma unroll
        for (int o = 16; o > 0; o >>= 1) s += __shfl_down_sync(0xffffffffu, s, o);
        if (t == 0) sbase = s;
    }
    __syncthreads();
    int base = sbase;
    int v = hist[t];
    __syncthreads();

    int x = v;
#pragma unroll
    for (int o = 1; o < 32; o <<= 1) {
        int y = __shfl_up_sync(0xffffffffu, x, o);
        if (lane >= o) x += y;
    }
    if (lane == 31) ws[wid] = x;
    __syncthreads();
    if (wid == 0) {
        int s = ws[lane];
        int xs = s;
#pragma unroll
        for (int o = 1; o < 32; o <<= 1) {
            int y = __shfl_up_sync(0xffffffffu, xs, o);
            if (lane >= o) xs += y;
        }
        ws[lane] = xs - s;
    }
    __syncthreads();
    int incl = x + ws[wid];
    int i = lo + t;
    if (i < NN) {
        g_rowptr[i] = base + incl - v;
        g_invdeg[i] = 1.0f / fmaxf((float)v, 1.0f);
        g_cursor[i] = 0;   // restore fill-cursor invariant (fused former k_zero_end)
    }
    if (b == 0 && t == 0) g_rowptr[NN] = EE;
}

// ---------------- fused prep ----------------
__global__ void k_prep(const int* __restrict__ src, const int* __restrict__ dst,
                       const float* __restrict__ x, const float* __restrict__ h,
                       const float* __restrict__ Wl, const float* __restrict__ Wr,
                       const float* __restrict__ b) {
    const int W1TN = LL * 384 * 512;
    const int W2TN = LL * 128 * 256;
    int i = blockIdx.x * blockDim.x + threadIdx.x;
    if (i < EE) {
        int d = dst[i];
        int p = atomicAdd(&g_cursor[d], 1);
        g_esrc[g_rowptr[d] + p] = src[i];
    } else if (i < EE + CONVN) {
        int j = i - EE;
        float4 v = __ldg((const float4*)x + j);
        store_h4(g_inp + (size_t)j * 4, v);
    } else if (i < EE + CONVN + LL * CONVN) {
        int j = i - EE - CONVN;
        float4 v = __ldg((const float4*)h + j);
        store_h4(g_h + (size_t)j * 4, v);
    } else {
        int j = i - EE - CONVN - LL * CONVN;
        if (j < W1TN) {
            int l = j / (384 * 512);
            int rem = j % (384 * 512);
            int c = rem / 512, k = rem % 512;
            int cb = c >> 7, cc = c & 127;
            int s = k >> 7, kk = k & 127;
            float v = 0.0f;
            if (!(cb == 2 && s >= 2)) {
                int g = cb * 2 + (s >> 1);
                const float* W = (s & 1) ? Wr : Wl;
                v = W[(((size_t)l * 6 + g) * 128 + kk) * 128 + cc];
            }
            g_W1T[j] = __float2half_rn(v);
        } else if (j < W1TN + W2TN) {
            int j2 = j - W1TN;
            int l = j2 / (128 * 256);
            int rem = j2 % (128 * 256);
            int c = rem / 256, k = rem % 256;
            int s = k >> 7, kk = k & 127;
            const float* W = s ? Wr : Wl;
            float v = W[(((size_t)l * 6 + 5) * 128 + kk) * 128 + c];
            g_W2T[j2] = __float2half_rn(v);
        } else if (j < W1TN + W2TN + LL * 384) {
            int j2 = j - W1TN - W2TN;
            int l = j2 / 384;
            int c = j2 % 384;
            int cb = c >> 7, cc = c & 127;
            g_bias[j2] = b[(((size_t)l * 6 + cb * 2) * 128) + cc] +
                         b[(((size_t)l * 6 + cb * 2 + 1) * 128) + cc];
        }
    }
}

// ---------------- aggregation ----------------
__global__ void k_agg2(int l) {
    int warp = (blockIdx.x * blockDim.x + threadIdx.x) >> 5;
    int lane = threadIdx.x & 31;
    if (warp >= NN) return;
    const __half* __restrict__ A = g_inp;
    const __half* __restrict__ B = g_h + (size_t)l * NN * DD;
    int e = g_rowptr[warp], end = g_rowptr[warp + 1];
    float4 aa = make_float4(0.f, 0.f, 0.f, 0.f);
    float4 ab = make_float4(0.f, 0.f, 0.f, 0.f);
#define ACC4(dst, v) do { \
        float2 _p0 = __half22float2(*(__half2*)&(v).x); \
        float2 _p1 = __half22float2(*(__half2*)&(v).y); \
        dst.x += _p0.x; dst.y += _p0.y; dst.z += _p1.x; dst.w += _p1.y; } while (0)
    for (; e + 3 < end; e += 4) {
        int s0 = g_esrc[e], s1 = g_esrc[e + 1], s2 = g_esrc[e + 2], s3 = g_esrc[e + 3];
        uint2 va0 = __ldg((const uint2*)(A + (size_t)s0 * DD) + lane);
        uint2 va1 = __ldg((const uint2*)(A + (size_t)s1 * DD) + lane);
        uint2 va2 = __ldg((const uint2*)(A + (size_t)s2 * DD) + lane);
        uint2 va3 = __ldg((const uint2*)(A + (size_t)s3 * DD) + lane);
        uint2 vb0 = __ldg((const uint2*)(B + (size_t)s0 * DD) + lane);
        uint2 vb1 = __ldg((const uint2*)(B + (size_t)s1 * DD) + lane);
        uint2 vb2 = __ldg((const uint2*)(B + (size_t)s2 * DD) + lane);
        uint2 vb3 = __ldg((const uint2*)(B + (size_t)s3 * DD) + lane);
        ACC4(aa, va0); ACC4(aa, va1); ACC4(aa, va2); ACC4(aa, va3);
        ACC4(ab, vb0); ACC4(ab, vb1); ACC4(ab, vb2); ACC4(ab, vb3);
    }
    for (; e < end; e++) {
        int s0 = g_esrc[e];
        uint2 va0 = __ldg((const uint2*)(A + (size_t)s0 * DD) + lane);
        uint2 vb0 = __ldg((const uint2*)(B + (size_t)s0 * DD) + lane);
        ACC4(aa, va0); ACC4(ab, vb0);
    }
    float sc = g_invdeg[warp];
    aa.x *= sc; aa.y *= sc; aa.z *= sc; aa.w *= sc;
    ab.x *= sc; ab.y *= sc; ab.z *= sc; ab.w *= sc;
    size_t o = (size_t)warp * DD + lane * 4;
    store_h4(g_agga + o, aa);
    store_h4(g_aggb + o, ab);
}

__global__ void k_agg1() {
    int warp = (blockIdx.x * blockDim.x + threadIdx.x) >> 5;
    int lane = threadIdx.x & 31;
    if (warp >= NN) return;
    int e = g_rowptr[warp], end = g_rowptr[warp + 1];
    float4 aa = make_float4(0.f, 0.f, 0.f, 0.f);
    for (; e + 3 < end; e += 4) {
        int s0 = g_esrc[e], s1 = g_esrc[e + 1], s2 = g_esrc[e + 2], s3 = g_esrc[e + 3];
        uint2 v0 = __ldg((const uint2*)(g_rh + (size_t)s0 * DD) + lane);
        uint2 v1 = __ldg((const uint2*)(g_rh + (size_t)s1 * DD) + lane);
        uint2 v2 = __ldg((const uint2*)(g_rh + (size_t)s2 * DD) + lane);
        uint2 v3 = __ldg((const uint2*)(g_rh + (size_t)s3 * DD) + lane);
        ACC4(aa, v0); ACC4(aa, v1); ACC4(aa, v2); ACC4(aa, v3);
    }
    for (; e < end; e++) {
        int s0 = g_esrc[e];
        uint2 v0 = __ldg((const uint2*)(g_rh + (size_t)s0 * DD) + lane);
        ACC4(aa, v0);
    }
    float sc = g_invdeg[warp];
    aa.x *= sc; aa.y *= sc; aa.z *= sc; aa.w *= sc;
    store_h4(g_agga + (size_t)warp * DD + lane * 4, aa);
}
#undef ACC4

// ---------------- HMMA core: 32x32 warp tile, one K32 stage ----------------
__device__ __forceinline__ void gemm_sub1(uint32_t sA, uint32_t lsm_a, uint32_t lsm_b,
                                          float acc[2][4][4]) {
    uint32_t sB = sA + ATB;
#pragma unroll
    for (int kb = 0; kb < 2; kb++) {
        uint32_t ko = kb * 32;
        uint32_t Af[2][4], Bf[2][4];
        ldsm4(Af[0], sA + lsm_a + ko);
        ldsm4(Af[1], sA + lsm_a + ko + 16 * TROW);
        ldsm4(Bf[0], sB + lsm_b + ko);
        ldsm4(Bf[1], sB + lsm_b + ko + 16 * TROW);
#pragma unroll
        for (int mt = 0; mt < 2; mt++)
#pragma unroll
            for (int nt = 0; nt < 4; nt++) {
                int ng = nt >> 1, o = nt & 1;
                mma16816(acc[mt][nt], Af[mt], Bf[ng][o], Bf[ng][o + 2]);
            }
    }
}

// ---------------- GEMM1: CTA 128x64, warp 32x32, 4 CTAs/SM, 3-stage K32 ring ----------------
__global__ void __launch_bounds__(256, 4)
k_gemm1(const float* __restrict__ hl, int l) {
    extern __shared__ __align__(16) char smdyn[];
    uint32_t sb = smem_u32(smdyn);
    int t = threadIdx.x;
    int row0 = blockIdx.y * 128;
    int cb64 = blockIdx.x;
    int col0 = cb64 * 64;
    int cb = cb64 >> 1;
    const int S = (cb == 2) ? 8 : 16;   // K32 steps

    const __half* __restrict__ W = g_W1T + (size_t)l * 384 * 512;
    const __half* segs[4] = { g_agga, g_inp, g_aggb, g_h + (size_t)l * NN * DD };

    const Pre p = make_pre(t, row0, col0, 512);
    int lane = t & 31, wid = t >> 5;
    int wm = wid & 3, wn = wid >> 2;
    uint32_t rsel = (uint32_t)(lane & 15) * TROW + (uint32_t)(lane >> 4) * 16;
    uint32_t lsm_a = (uint32_t)(wm * 32) * TROW + rsel;
    uint32_t lsm_b = (uint32_t)(wn * 32) * TROW + rsel;

    float acc[2][4][4];
#pragma unroll
    for (int i = 0; i < 2; i++)
#pragma unroll
        for (int j = 0; j < 4; j++)
#pragma unroll
            for (int q = 0; q < 4; q++) acc[i][j][q] = 0.0f;

    // prologue: stages 0,1
#pragma unroll
    for (int s = 0; s < 2; s++) {
        load_sub1(sb + s * SUB1, segs[s >> 2], W, (s & 3) * 32, s * 32, p);
        CPA_COMMIT();
    }
    int bs = 0;          // s % 3
    int bn = 2;          // (s+2) % 3
    for (int s = 0; s < S; s++) {
        CPA_WAIT1();          // stage s resident (all but 1 newest group done)
        __syncthreads();      // all warps finished compute(s-1) -> buf[(s+2)%3] reusable
        int sn = s + 2;
        if (sn < S)
            load_sub1(sb + bn * SUB1, segs[sn >> 2], W, (sn & 3) * 32, sn * 32, p);
        CPA_COMMIT();         // always commit to keep the group-count invariant
        gemm_sub1(sb + bs * SUB1, lsm_a, lsm_b, acc);
        bs = (bs == 2) ? 0 : bs + 1;
        bn = (bn == 2) ? 0 : bn + 1;
    }

    // epilogue
    const float* bias = g_bias + l * 384;
#pragma unroll
    for (int mt = 0; mt < 2; mt++)
#pragma unroll
        for (int nt = 0; nt < 4; nt++) {
            int row = row0 + wm * 32 + mt * 16 + (lane >> 2);
            int col = col0 + wn * 32 + nt * 8 + (lane & 3) * 2;
            float b0 = __ldg(bias + col), b1 = __ldg(bias + col + 1);
            int ccol = col & 127;
#pragma unroll
            for (int half = 0; half < 2; half++) {
                int r = row + half * 8;
                if (r >= NN) continue;
                float v0 = acc[mt][nt][half * 2 + 0] + b0;
                float v1 = acc[mt][nt][half * 2 + 1] + b1;
                size_t idx = (size_t)r * 128 + ccol;
                if (cb == 0) {
                    store_h2(g_Z + idx, sigf(v0), sigf(v1));
                } else if (cb == 1) {
                    float h0 = hl[idx], h1 = hl[idx + 1];
                    store_h2(g_rh + idx, sigf(v0) * h0, sigf(v1) * h1);
                } else {
                    store_h2(g_HX + idx, v0, v1);
                }
            }
        }
}

// ---------------- GEMM2: CTA 128x64, warp 32x32, 4 CTAs/SM, 3-stage K32 ring ----------------
__global__ void __launch_bounds__(256, 4)
k_gemm2(const float* __restrict__ hl, float* __restrict__ out, int l) {
    extern __shared__ __align__(16) char smdyn[];
    uint32_t sb = smem_u32(smdyn);
    int t = threadIdx.x;
    int row0 = blockIdx.y * 128;
    int col0 = blockIdx.x * 64;
    const int S = 8;

    const __half* __restrict__ W = g_W2T + (size_t)l * 128 * 256;
    const __half* segs[2] = { g_agga, g_rh };

    const Pre p = make_pre(t, row0, col0, 256);
    int lane = t & 31, wid = t >> 5;
    int wm = wid & 3, wn = wid >> 2;
    uint32_t rsel = (uint32_t)(lane & 15) * TROW + (uint32_t)(lane >> 4) * 16;
    uint32_t lsm_a = (uint32_t)(wm * 32) * TROW + rsel;
    uint32_t lsm_b = (uint32_t)(wn * 32) * TROW + rsel;

    float acc[2][4][4];
#pragma unroll
    for (int i = 0; i < 2; i++)
#pragma unroll
        for (int j = 0; j < 4; j++)
#pragma unroll
            for (int q = 0; q < 4; q++) acc[i][j][q] = 0.0f;

#pragma unroll
    for (int s = 0; s < 2; s++) {
        load_sub1(sb + s * SUB1, segs[s >> 2], W, (s & 3) * 32, s * 32, p);
        CPA_COMMIT();
    }
    int bs = 0, bn = 2;
    for (int s = 0; s < S; s++) {
        CPA_WAIT1();
        __syncthreads();
        int sn = s + 2;
        if (sn < S)
            load_sub1(sb + bn * SUB1, segs[sn >> 2], W, (sn & 3) * 32, sn * 32, p);
        CPA_COMMIT();
        gemm_sub1(sb + bs * SUB1, lsm_a, lsm_b, acc);
        bs = (bs == 2) ? 0 : bs + 1;
        bn = (bn == 2) ? 0 : bn + 1;
    }

#pragma unroll
    for (int mt = 0; mt < 2; mt++)
#pragma unroll
        for (int nt = 0; nt < 4; nt++) {
            int row = row0 + wm * 32 + mt * 16 + (lane >> 2);
            int col = col0 + wn * 32 + nt * 8 + (lane & 3) * 2;
#pragma unroll
            for (int half = 0; half < 2; half++) {
                int r = row + half * 8;
                if (r >= NN) continue;
                size_t idx = (size_t)r * 128 + col;
                float2 hx = __half22float2(*(const __half2*)(g_HX + idx));
                float2 zz = __half22float2(*(const __half2*)(g_Z + idx));
                float h0 = hl[idx], h1 = hl[idx + 1];
                float ht0 = tanh_fast(acc[mt][nt][half * 2 + 0] + hx.x);
                float ht1 = tanh_fast(acc[mt][nt][half * 2 + 1] + hx.y);
                float o0 = zz.x * h0 + (1.0f - zz.x) * ht0;
                float o1 = zz.y * h1 + (1.0f - zz.y) * ht1;
                *(float2*)(out + idx) = make_float2(o0, o1);
                store_h2(g_inp + idx, o0, o1);
            }
        }
}

// ---------------- launch ----------------
extern "C" void kernel_launch(void* const* d_in, const int* in_sizes, int n_in,
                              void* d_out, int out_size) {
    const float* x  = (const float*)d_in[0];
    const float* h  = (const float*)d_in[1];
    const float* Wl = (const float*)d_in[2];
    const float* Wr = (const float*)d_in[3];
    const float* b  = (const float*)d_in[4];
    const int* src  = (const int*)d_in[5];
    const int* dst  = (const int*)d_in[6];
    float* out = (float*)d_out;

    cudaFuncSetAttribute(k_gemm1, cudaFuncAttributeMaxDynamicSharedMemorySize, GSMEM1);
    cudaFuncSetAttribute(k_gemm2, cudaFuncAttributeMaxDynamicSharedMemorySize, GSMEM1);

    const int ROWT = (NN + 127) / 128;
    const int WTOT = LL * 384 * 512 + LL * 128 * 256 + LL * 384;
    const int PREPN = EE + CONVN + LL * CONVN + WTOT;

    k_countscan<<<NCHUNK, 1024>>>(dst);
    k_prep<<<(PREPN + 255) / 256, 256>>>(src, dst, x, h, Wl, Wr, b);

    for (int l = 0; l < LL; l++) {
        const float* hl = h + (size_t)l * NN * DD;
        k_agg2<<<(NN * 32 + 255) / 256, 256>>>(l);
        dim3 g1(6, ROWT);
        k_gemm1<<<g1, 256, GSMEM1>>>(hl, l);   // launch #4 <- ncu target
        k_agg1<<<(NN * 32 + 255) / 256, 256>>>();
        dim3 g2(2, ROWT);
        k_gemm2<<<g2, 256, GSMEM1>>>(hl, out + (size_t)l * NN * DD, l);
    }
}

// round 17
// speedup vs baseline: 1.0004x; 1.0004x over previous
#include <cuda_runtime.h>
#include <cuda_fp16.h>
#include <math.h>
#include <stdint.h>

// Problem constants (fixed by setup_inputs)
#define NN 50000
#define EE 800000
#define DD 128
#define LL 2
#define NCHUNK ((NN + 1023) / 1024)
#define CONVN (NN * DD / 4)

// ---------------- scratch (static __device__ globals; no allocation) ----------------
// g_cursor zeroed inside k_countscan each call (module-load zero-init covers call #1).
__device__ float g_bias[LL * 384];
__device__ float g_invdeg[NN];
__device__ int g_rowptr[NN + 1];
__device__ int g_cursor[NN];
__device__ int g_esrc[EE];

__device__ __align__(16) __half g_Z[NN * DD];
__device__ __align__(16) __half g_HX[NN * DD];
__device__ __align__(16) __half g_inp[NN * DD];
__device__ __align__(16) __half g_h[LL * NN * DD];
__device__ __align__(16) __half g_agga[NN * DD];
__device__ __align__(16) __half g_aggb[NN * DD];
__device__ __align__(16) __half g_rh[NN * DD];
__device__ __align__(16) __half g_W1T[LL * 384 * 512];
__device__ __align__(16) __half g_W2T[LL * 128 * 256];

// ---------------- helpers ----------------
__device__ __forceinline__ uint32_t smem_u32(const void* p) {
    uint32_t a;
    asm("{ .reg .u64 t; cvta.to.shared.u64 t, %1; cvt.u32.u64 %0, t; }" : "=r"(a) : "l"(p));
    return a;
}
__device__ __forceinline__ void ldsm4(uint32_t* f, uint32_t addr) {
    asm volatile("ldmatrix.sync.aligned.m8n8.x4.shared.b16 {%0,%1,%2,%3}, [%4];"
                 : "=r"(f[0]), "=r"(f[1]), "=r"(f[2]), "=r"(f[3]) : "r"(addr));
}
__device__ __forceinline__ void mma16816(float* c, const uint32_t* a, uint32_t b0, uint32_t b1) {
    asm volatile(
        "mma.sync.aligned.m16n8k16.row.col.f32.f16.f16.f32 "
        "{%0,%1,%2,%3}, {%4,%5,%6,%7}, {%8,%9}, {%0,%1,%2,%3};"
        : "+f"(c[0]), "+f"(c[1]), "+f"(c[2]), "+f"(c[3])
        : "r"(a[0]), "r"(a[1]), "r"(a[2]), "r"(a[3]), "r"(b0), "r"(b1));
}
__device__ __forceinline__ void cpa16(uint32_t dst, const void* src, int sz) {
    asm volatile("cp.async.cg.shared.global [%0], [%1], 16, %2;"
                 :: "r"(dst), "l"(src), "r"(sz) : "memory");
}
#define CPA_COMMIT() asm volatile("cp.async.commit_group;" ::: "memory")
#define CPA_WAIT2()  asm volatile("cp.async.wait_group 2;" ::: "memory")

__device__ __forceinline__ void store_h4(__half* d, float4 v) {
    __half2 h0 = __floats2half2_rn(v.x, v.y);
    __half2 h1 = __floats2half2_rn(v.z, v.w);
    uint2 u;
    u.x = *(uint32_t*)&h0;
    u.y = *(uint32_t*)&h1;
    *(uint2*)d = u;
}
__device__ __forceinline__ void store_h2(__half* d, float a, float b) {
    __half2 hh = __floats2half2_rn(a, b);
    *(uint32_t*)d = *(uint32_t*)&hh;
}
// fast MUFU-path transcendentals
__device__ __forceinline__ float sigf(float x) { return 1.0f / (1.0f + __expf(-x)); }
__device__ __forceinline__ float tanh_fast(float x) {
    float t = __expf(2.0f * x);
    return 1.0f - 2.0f / (t + 1.0f);
}

// SMEM tile geometry: padded row stride 80B (conflict-free ldmatrix)
#define TROW 80
#define ATB (128 * TROW)           // A subtile: 128 rows x 32 cols  (10240)
#define BTB (64 * TROW)            // B subtile: 64 rows x 32 cols (5120)
#define SUB1 (ATB + BTB)           // 15360: one K32 pipeline stage
#define GSMEM1 (4 * SUB1)          // 61440: 4-stage ring (R15 config, 3 CTAs/SM)

// precomputed per-thread tile-load state
struct Pre {
    uint32_t sm0, sm1;
    uint32_t a0, a1;
    int az0, az1;
    uint32_t b0, b1;
};

__device__ __forceinline__ Pre make_pre(int t, int row0, int col0, int strideB) {
    Pre p;
    int q = t & 3;
    int r0 = t >> 2, r1 = r0 + 64;
    p.sm0 = (uint32_t)(r0 * TROW + q * 16);
    p.sm1 = (uint32_t)(r1 * TROW + q * 16);
    int gr0 = row0 + r0, gr1 = row0 + r1;
    p.az0 = gr0 < NN ? 16 : 0;
    p.az1 = gr1 < NN ? 16 : 0;
    if (gr0 >= NN) gr0 = 0;
    if (gr1 >= NN) gr1 = 0;
    p.a0 = (uint32_t)(gr0 * 128 + q * 8);
    p.a1 = (uint32_t)(gr1 * 128 + q * 8);
    p.b0 = (uint32_t)((col0 + r0) * strideB + q * 8);
    p.b1 = (uint32_t)((col0 + r1) * strideB + q * 8);
    return p;
}

// one K32 stage: A 128x32 + B 64x32
__device__ __forceinline__ void load_sub1(uint32_t buf,
                                          const __half* __restrict__ a,
                                          const __half* __restrict__ b,
                                          int colA, int colB, const Pre& p) {
    cpa16(buf + p.sm0,       a + p.a0 + colA, p.az0);
    cpa16(buf + p.sm1,       a + p.a1 + colA, p.az1);
    cpa16(buf + ATB + p.sm0, b + p.b0 + colB, 16);
}

// ---------------- CSR: fused count+scan (+ cursor zeroing) ----------------
__global__ void __launch_bounds__(1024)
k_countscan(const int* __restrict__ dst) {
    __shared__ int hist[1024];
    __shared__ int ws[32];
    __shared__ int sbase;
    int b = blockIdx.x, t = threadIdx.x;
    int lane = t & 31, wid = t >> 5;
    hist[t] = 0;
    __syncthreads();

    int lo = b << 10;
    int pre = 0;
    const int4* d4 = (const int4*)dst;
    for (int e = t; e < EE / 4; e += 1024) {
        int4 v = __ldg(d4 + e);
        pre += (v.x < lo) + (v.y < lo) + (v.z < lo) + (v.w < lo);
        int dx;
        dx = v.x - lo; if ((unsigned)dx < 1024u) atomicAdd(&hist[dx], 1);
        dx = v.y - lo; if ((unsigned)dx < 1024u) atomicAdd(&hist[dx], 1);
        dx = v.z - lo; if ((unsigned)dx < 1024u) atomicAdd(&hist[dx], 1);
        dx = v.w - lo; if ((unsigned)dx < 1024u) atomicAdd(&hist[dx], 1);
    }
#pragma unroll
    for (int o = 16; o > 0; o >>= 1) pre += __shfl_down_sync(0xffffffffu, pre, o);
    if (lane == 0) ws[wid] = pre;
    __syncthreads();
    if (t < 32) {
        int s = ws[t];
#pragma unroll
        for (int o = 16; o > 0; o >>= 1) s += __shfl_down_sync(0xffffffffu, s, o);
        if (t == 0) sbase = s;
    }
    __syncthreads();
    int base = sbase;
    int v = hist[t];
    __syncthreads();

    int x = v;
#pragma unroll
    for (int o = 1; o < 32; o <<= 1) {
        int y = __shfl_up_sync(0xffffffffu, x, o);
        if (lane >= o) x += y;
    }
    if (lane == 31) ws[wid] = x;
    __syncthreads();
    if (wid == 0) {
        int s = ws[lane];
        int xs = s;
#pragma unroll
        for (int o = 1; o < 32; o <<= 1) {
            int y = __shfl_up_sync(0xffffffffu, xs, o);
            if (lane >= o) xs += y;
        }
        ws[lane] = xs - s;
    }
    __syncthreads();
    int incl = x + ws[wid];
    int i = lo + t;
    if (i < NN) {
        g_rowptr[i] = base + incl - v;
        g_invdeg[i] = 1.0f / fmaxf((float)v, 1.0f);
        g_cursor[i] = 0;
    }
    if (b == 0 && t == 0) g_rowptr[NN] = EE;
}

// ---------------- fused prep ----------------
__global__ void k_prep(const int* __restrict__ src, const int* __restrict__ dst,
                       const float* __restrict__ x, const float* __restrict__ h,
                       const float* __restrict__ Wl, const float* __restrict__ Wr,
                       const float* __restrict__ b) {
    const int W1TN = LL * 384 * 512;
    const int W2TN = LL * 128 * 256;
    int i = blockIdx.x * blockDim.x + threadIdx.x;
    if (i < EE) {
        int d = dst[i];
        int p = atomicAdd(&g_cursor[d], 1);
        g_esrc[g_rowptr[d] + p] = src[i];
    } else if (i < EE + CONVN) {
        int j = i - EE;
        float4 v = __ldg((const float4*)x + j);
        store_h4(g_inp + (size_t)j * 4, v);
    } else if (i < EE + CONVN + LL * CONVN) {
        int j = i - EE - CONVN;
        float4 v = __ldg((const float4*)h + j);
        store_h4(g_h + (size_t)j * 4, v);
    } else {
        int j = i - EE - CONVN - LL * CONVN;
        if (j < W1TN) {
            int l = j / (384 * 512);
            int rem = j % (384 * 512);
            int c = rem / 512, k = rem % 512;
            int cb = c >> 7, cc = c & 127;
            int s = k >> 7, kk = k & 127;
            float v = 0.0f;
            if (!(cb == 2 && s >= 2)) {
                int g = cb * 2 + (s >> 1);
                const float* W = (s & 1) ? Wr : Wl;
                v = W[(((size_t)l * 6 + g) * 128 + kk) * 128 + cc];
            }
            g_W1T[j] = __float2half_rn(v);
        } else if (j < W1TN + W2TN) {
            int j2 = j - W1TN;
            int l = j2 / (128 * 256);
            int rem = j2 % (128 * 256);
            int c = rem / 256, k = rem % 256;
            int s = k >> 7, kk = k & 127;
            const float* W = s ? Wr : Wl;
            float v = W[(((size_t)l * 6 + 5) * 128 + kk) * 128 + c];
            g_W2T[j2] = __float2half_rn(v);
        } else if (j < W1TN + W2TN + LL * 384) {
            int j2 = j - W1TN - W2TN;
            int l = j2 / 384;
            int c = j2 % 384;
            int cb = c >> 7, cc = c & 127;
            g_bias[j2] = b[(((size_t)l * 6 + cb * 2) * 128) + cc] +
                         b[(((size_t)l * 6 + cb * 2 + 1) * 128) + cc];
        }
    }
}

// ---------------- aggregation ----------------
// unpack uint4 (8 halves) into 8-float accumulator
#define ACCU8(acc, v) do { \
    float2 f0 = __half22float2(*(__half2*)&(v).x); \
    float2 f1 = __half22float2(*(__half2*)&(v).y); \
    float2 f2 = __half22float2(*(__half2*)&(v).z); \
    float2 f3 = __half22float2(*(__half2*)&(v).w); \
    acc[0] += f0.x; acc[1] += f0.y; acc[2] += f1.x; acc[3] += f1.y; \
    acc[4] += f2.x; acc[5] += f2.y; acc[6] += f3.x; acc[7] += f3.y; } while (0)

// agg2: warp per node; lanes 0-15 gather the A row (16B each), lanes 16-31 the B row.
// One uint4 LDG per lane per edge (was two uint2).
__global__ void k_agg2(int l) {
    int warp = (blockIdx.x * blockDim.x + threadIdx.x) >> 5;
    int lane = threadIdx.x & 31;
    if (warp >= NN) return;
    const __half* __restrict__ base =
        (lane < 16) ? g_inp : (g_h + (size_t)l * NN * DD);
    int colo = (lane & 15) * 8;
    int e = g_rowptr[warp], end = g_rowptr[warp + 1];
    float acc[8];
#pragma unroll
    for (int j = 0; j < 8; j++) acc[j] = 0.0f;
    for (; e + 3 < end; e += 4) {
        int s0 = g_esrc[e], s1 = g_esrc[e + 1], s2 = g_esrc[e + 2], s3 = g_esrc[e + 3];
        uint4 v0 = __ldg((const uint4*)(base + (size_t)s0 * DD + colo));
        uint4 v1 = __ldg((const uint4*)(base + (size_t)s1 * DD + colo));
        uint4 v2 = __ldg((const uint4*)(base + (size_t)s2 * DD + colo));
        uint4 v3 = __ldg((const uint4*)(base + (size_t)s3 * DD + colo));
        ACCU8(acc, v0); ACCU8(acc, v1); ACCU8(acc, v2); ACCU8(acc, v3);
    }
    for (; e < end; e++) {
        int s0 = g_esrc[e];
        uint4 v0 = __ldg((const uint4*)(base + (size_t)s0 * DD + colo));
        ACCU8(acc, v0);
    }
    float sc = g_invdeg[warp];
    __half2 h0 = __floats2half2_rn(acc[0] * sc, acc[1] * sc);
    __half2 h1 = __floats2half2_rn(acc[2] * sc, acc[3] * sc);
    __half2 h2 = __floats2half2_rn(acc[4] * sc, acc[5] * sc);
    __half2 h3 = __floats2half2_rn(acc[6] * sc, acc[7] * sc);
    uint4 o;
    o.x = *(uint32_t*)&h0; o.y = *(uint32_t*)&h1;
    o.z = *(uint32_t*)&h2; o.w = *(uint32_t*)&h3;
    __half* dst = ((lane < 16) ? g_agga : g_aggb) + (size_t)warp * DD + colo;
    *(uint4*)dst = o;
}

// agg1: warp per node; half-warps process two consecutive edges (uint4 per lane,
// 16 lanes cover the row); final shfl_down(16) combines.
__global__ void k_agg1() {
    int warp = (blockIdx.x * blockDim.x + threadIdx.x) >> 5;
    int lane = threadIdx.x & 31;
    if (warp >= NN) return;
    int hid = lane >> 4;          // 0 or 1: which edge of the pair
    int colo = (lane & 15) * 8;
    int e0 = g_rowptr[warp], end = g_rowptr[warp + 1];
    float acc[8];
#pragma unroll
    for (int j = 0; j < 8; j++) acc[j] = 0.0f;
    for (int e = e0; e < end; e += 4) {
        int ea = e + hid, eb = e + 2 + hid;
        bool pa = ea < end, pb = eb < end;
        int sa = g_esrc[pa ? ea : e0];
        int sb = g_esrc[pb ? eb : e0];
        uint4 va = __ldg((const uint4*)(g_rh + (size_t)sa * DD + colo));
        uint4 vb = __ldg((const uint4*)(g_rh + (size_t)sb * DD + colo));
        if (pa) ACCU8(acc, va);
        if (pb) ACCU8(acc, vb);
    }
    // combine the two half-warps
#pragma unroll
    for (int j = 0; j < 8; j++)
        acc[j] += __shfl_down_sync(0xffffffffu, acc[j], 16);
    if (lane < 16) {
        float sc = g_invdeg[warp];
        __half2 h0 = __floats2half2_rn(acc[0] * sc, acc[1] * sc);
        __half2 h1 = __floats2half2_rn(acc[2] * sc, acc[3] * sc);
        __half2 h2 = __floats2half2_rn(acc[4] * sc, acc[5] * sc);
        __half2 h3 = __floats2half2_rn(acc[6] * sc, acc[7] * sc);
        uint4 o;
        o.x = *(uint32_t*)&h0; o.y = *(uint32_t*)&h1;
        o.z = *(uint32_t*)&h2; o.w = *(uint32_t*)&h3;
        *(uint4*)(g_agga + (size_t)warp * DD + colo) = o;
    }
}
#undef ACCU8

// ---------------- HMMA core: 32x32 warp tile, one K32 stage ----------------
__device__ __forceinline__ void gemm_sub1(uint32_t sA, uint32_t lsm_a, uint32_t lsm_b,
                                          float acc[2][4][4]) {
    uint32_t sB = sA + ATB;
#pragma unroll
    for (int kb = 0; kb < 2; kb++) {
        uint32_t ko = kb * 32;
        uint32_t Af[2][4], Bf[2][4];
        ldsm4(Af[0], sA + lsm_a + ko);
        ldsm4(Af[1], sA + lsm_a + ko + 16 * TROW);
        ldsm4(Bf[0], sB + lsm_b + ko);
        ldsm4(Bf[1], sB + lsm_b + ko + 16 * TROW);
#pragma unroll
        for (int mt = 0; mt < 2; mt++)
#pragma unroll
            for (int nt = 0; nt < 4; nt++) {
                int ng = nt >> 1, o = nt & 1;
                mma16816(acc[mt][nt], Af[mt], Bf[ng][o], Bf[ng][o + 2]);
            }
    }
}

// ---------------- GEMM1: CTA 128x64, warp 32x32, 3 CTAs/SM, 4-stage K32 (R15) ----------------
__global__ void __launch_bounds__(256, 3)
k_gemm1(const float* __restrict__ hl, int l) {
    extern __shared__ __align__(16) char smdyn[];
    uint32_t sb = smem_u32(smdyn);
    int t = threadIdx.x;
    int row0 = blockIdx.y * 128;
    int cb64 = blockIdx.x;
    int col0 = cb64 * 64;
    int cb = cb64 >> 1;
    const int S = (cb == 2) ? 8 : 16;

    const __half* __restrict__ W = g_W1T + (size_t)l * 384 * 512;
    const __half* segs[4] = { g_agga, g_inp, g_aggb, g_h + (size_t)l * NN * DD };

    const Pre p = make_pre(t, row0, col0, 512);
    int lane = t & 31, wid = t >> 5;
    int wm = wid & 3, wn = wid >> 2;
    uint32_t rsel = (uint32_t)(lane & 15) * TROW + (uint32_t)(lane >> 4) * 16;
    uint32_t lsm_a = (uint32_t)(wm * 32) * TROW + rsel;
    uint32_t lsm_b = (uint32_t)(wn * 32) * TROW + rsel;

    float acc[2][4][4];
#pragma unroll
    for (int i = 0; i < 2; i++)
#pragma unroll
        for (int j = 0; j < 4; j++)
#pragma unroll
            for (int q = 0; q < 4; q++) acc[i][j][q] = 0.0f;

#pragma unroll
    for (int s = 0; s < 3; s++) {
        load_sub1(sb + s * SUB1, segs[s >> 2], W, (s & 3) * 32, s * 32, p);
        CPA_COMMIT();
    }
    for (int s = 0; s < S; s++) {
        CPA_WAIT2();
        __syncthreads();
        int sn = s + 3;
        if (sn < S)
            load_sub1(sb + (sn & 3) * SUB1, segs[sn >> 2], W, (sn & 3) * 32, sn * 32, p);
        CPA_COMMIT();
        gemm_sub1(sb + (s & 3) * SUB1, lsm_a, lsm_b, acc);
    }

    // epilogue
    const float* bias = g_bias + l * 384;
#pragma unroll
    for (int mt = 0; mt < 2; mt++)
#pragma unroll
        for (int nt = 0; nt < 4; nt++) {
            int row = row0 + wm * 32 + mt * 16 + (lane >> 2);
            int col = col0 + wn * 32 + nt * 8 + (lane & 3) * 2;
            float b0 = __ldg(bias + col), b1 = __ldg(bias + col + 1);
            int ccol = col & 127;
#pragma unroll
            for (int half = 0; half < 2; half++) {
                int r = row + half * 8;
                if (r >= NN) continue;
                float v0 = acc[mt][nt][half * 2 + 0] + b0;
                float v1 = acc[mt][nt][half * 2 + 1] + b1;
                size_t idx = (size_t)r * 128 + ccol;
                if (cb == 0) {
                    store_h2(g_Z + idx, sigf(v0), sigf(v1));
                } else if (cb == 1) {
                    float h0 = hl[idx], h1 = hl[idx + 1];
                    store_h2(g_rh + idx, sigf(v0) * h0, sigf(v1) * h1);
                } else {
                    store_h2(g_HX + idx, v0, v1);
                }
            }
        }
}

// ---------------- GEMM2: CTA 128x64, warp 32x32, 3 CTAs/SM, 4-stage K32 (R15) ----------------
__global__ void __launch_bounds__(256, 3)
k_gemm2(const float* __restrict__ hl, float* __restrict__ out, int l) {
    extern __shared__ __align__(16) char smdyn[];
    uint32_t sb = smem_u32(smdyn);
    int t = threadIdx.x;
    int row0 = blockIdx.y * 128;
    int col0 = blockIdx.x * 64;
    const int S = 8;

    const __half* __restrict__ W = g_W2T + (size_t)l * 128 * 256;
    const __half* segs[2] = { g_agga, g_rh };

    const Pre p = make_pre(t, row0, col0, 256);
    int lane = t & 31, wid = t >> 5;
    int wm = wid & 3, wn = wid >> 2;
    uint32_t rsel = (uint32_t)(lane & 15) * TROW + (uint32_t)(lane >> 4) * 16;
    uint32_t lsm_a = (uint32_t)(wm * 32) * TROW + rsel;
    uint32_t lsm_b = (uint32_t)(wn * 32) * TROW + rsel;

    float acc[2][4][4];
#pragma unroll
    for (int i = 0; i < 2; i++)
#pragma unroll
        for (int j = 0; j < 4; j++)
#pragma unroll
            for (int q = 0; q < 4; q++) acc[i][j][q] = 0.0f;

#pragma unroll
    for (int s = 0; s < 3; s++) {
        load_sub1(sb + s * SUB1, segs[s >> 2], W, (s & 3) * 32, s * 32, p);
        CPA_COMMIT();
    }
    for (int s = 0; s < S; s++) {
        CPA_WAIT2();
        __syncthreads();
        int sn = s + 3;
        if (sn < S)
            load_sub1(sb + (sn & 3) * SUB1, segs[sn >> 2], W, (sn & 3) * 32, sn * 32, p);
        CPA_COMMIT();
        gemm_sub1(sb + (s & 3) * SUB1, lsm_a, lsm_b, acc);
    }

#pragma unroll
    for (int mt = 0; mt < 2; mt++)
#pragma unroll
        for (int nt = 0; nt < 4; nt++) {
            int row = row0 + wm * 32 + mt * 16 + (lane >> 2);
            int col = col0 + wn * 32 + nt * 8 + (lane & 3) * 2;
#pragma unroll
            for (int half = 0; half < 2; half++) {
                int r = row + half * 8;
                if (r >= NN) continue;
                size_t idx = (size_t)r * 128 + col;
                float2 hx = __half22float2(*(const __half2*)(g_HX + idx));
                float2 zz = __half22float2(*(const __half2*)(g_Z + idx));
                float h0 = hl[idx], h1 = hl[idx + 1];
                float ht0 = tanh_fast(acc[mt][nt][half * 2 + 0] + hx.x);
                float ht1 = tanh_fast(acc[mt][nt][half * 2 + 1] + hx.y);
                float o0 = zz.x * h0 + (1.0f - zz.x) * ht0;
                float o1 = zz.y * h1 + (1.0f - zz.y) * ht1;
                *(float2*)(out + idx) = make_float2(o0, o1);
                store_h2(g_inp + idx, o0, o1);
            }
        }
}

// ---------------- launch ----------------
extern "C" void kernel_launch(void* const* d_in, const int* in_sizes, int n_in,
                              void* d_out, int out_size) {
    const float* x  = (const float*)d_in[0];
    const float* h  = (const float*)d_in[1];
    const float* Wl = (const float*)d_in[2];
    const float* Wr = (const float*)d_in[3];
    const float* b  = (const float*)d_in[4];
    const int* src  = (const int*)d_in[5];
    const int* dst  = (const int*)d_in[6];
    float* out = (float*)d_out;

    cudaFuncSetAttribute(k_gemm1, cudaFuncAttributeMaxDynamicSharedMemorySize, GSMEM1);
    cudaFuncSetAttribute(k_gemm2, cudaFuncAttributeMaxDynamicSharedMemorySize, GSMEM1);

    const int ROWT = (NN + 127) / 128;
    const int WTOT = LL * 384 * 512 + LL * 128 * 256 + LL * 384;
    const int PREPN = EE + CONVN + LL * CONVN + WTOT;

    k_countscan<<<NCHUNK, 1024>>>(dst);
    k_prep<<<(PREPN + 255) / 256, 256>>>(src, dst, x, h, Wl, Wr, b);

    for (int l = 0; l < LL; l++) {
        const float* hl = h + (size_t)l * NN * DD;
        k_agg2<<<(NN * 32 + 255) / 256, 256>>>(l);
        dim3 g1(6, ROWT);
        k_gemm1<<<g1, 256, GSMEM1>>>(hl, l);   // launch #4 <- ncu target
        k_agg1<<<(NN * 32 + 255) / 256, 256>>>();
        dim3 g2(2, ROWT);
        k_gemm2<<<g2, 256, GSMEM1>>>(hl, out + (size_t)l * NN * DD, l);
    }
}